// round 14
// baseline (speedup 1.0000x reference)
#include <cuda_runtime.h>
#include <cuda_bf16.h>
#include <math.h>

#define B 64
#define C 256
#define D 128
#define KTOP 8
#define G2 148
#define TILE 128
#define NCAND (G2*KTOP)          // 1184
#define M1 24                    // exact-rescore window
#define QWW 36                   // Q^T bf16 row stride in words (64 bf16 + pad)
#define KWW 68                   // K^T bf16 row stride in words (128 bf16 + pad)
#define SIM_LD 132               // sims fp32 row stride

// smem word offsets (dynamic smem, sim kernel)
#define OFF_QT   0               // Q^T bf16 [d][m]: 128 x 36 = 4608
#define OFF_K0   4608            // K^T bf16 [d][n]: 128 x 68 = 8704
#define OFF_K1   13312
#define OFF_SSQ  22016           // ssq partials fp32 [buf][8][132] = 2112
#define OFF_IMP  24128           // importance fp32 [buf][128] = 256
#define OFF_SCL  24384           // scale fp32 [buf][128] = 256
#define OFF_SIM  24640           // sims fp32 [64][132] = 8448
#define SMEM_WORDS 33088         // 132352 B -> 1 CTA/SM

// scratch (device globals: no allocations allowed)
__device__ float          g_qRow[B*D];    // q (unnormalized) [b][d] fp32 (rescore)
__device__ __nv_bfloat16  g_qTbf[D*B];    // q^T bf16 [d][b] (GEMM operand)
__device__ float g_cval[B*NCAND];         // per-block top-8 values
__device__ int   g_cidx[B*NCAND];         // per-block top-8 indices

__device__ __forceinline__ float warpsum(float v) {
    v += __shfl_xor_sync(0xffffffff, v, 16);
    v += __shfl_xor_sync(0xffffffff, v, 8);
    v += __shfl_xor_sync(0xffffffff, v, 4);
    v += __shfl_xor_sync(0xffffffff, v, 2);
    v += __shfl_xor_sync(0xffffffff, v, 1);
    return v;
}

#define CVT2(w, h, l) \
    asm("cvt.rn.bf16x2.f32 %0, %1, %2;" : "=r"(w) : "f"(h), "f"(l))

// ---------------------------------------------------------------------------
// Kernel 1: q = query @ W_q^T + b_q  (no normalization: positive per-row scale
// is top-k order invariant and sim values are selection-only)
// ---------------------------------------------------------------------------
__global__ void qproj_kernel(const float* __restrict__ query,
                             const float* __restrict__ Wq,
                             const float* __restrict__ bq) {
    const int gw   = (blockIdx.x * blockDim.x + threadIdx.x) >> 5;  // 0..4095
    const int lane = threadIdx.x & 31;
    const int b    = gw >> 6;
    const int d0   = (gw & 63) << 1;

    const float* qr = query + (size_t)b * C;
    const float* w0 = Wq + (size_t)(d0 + 0) * C;
    const float* w1 = Wq + (size_t)(d0 + 1) * C;

    float a0 = 0.f, a1 = 0.f;
    #pragma unroll
    for (int j = 0; j < 8; j++) {
        int c = lane + 32 * j;
        float q = __ldg(qr + c);
        a0 += q * __ldg(w0 + c);
        a1 += q * __ldg(w1 + c);
    }
    #pragma unroll
    for (int off = 16; off; off >>= 1) {
        a0 += __shfl_xor_sync(0xffffffff, a0, off);
        a1 += __shfl_xor_sync(0xffffffff, a1, off);
    }
    if (lane == 0) {
        float v0 = a0 + bq[d0 + 0], v1 = a1 + bq[d0 + 1];
        g_qRow[b*D + d0 + 0] = v0;
        g_qRow[b*D + d0 + 1] = v1;
        g_qTbf[(d0 + 0)*B + b] = __float2bfloat16(v0);
        g_qTbf[(d0 + 1)*B + b] = __float2bfloat16(v1);
    }
}

// ---------------------------------------------------------------------------
// Kernel 2: 64x128 sim tile via HFMA2 bf16x2 SIMT GEMM (128 MAC/cyc/SM, 2x the
// emulated legacy-mma rate on sm_103). Transposed operands for LDS-lean
// fragments; dual bf16x2 accumulator chains + fp32 combine; LDG of next tile
// hidden behind GEMM; running top-8 per row stream.
// ---------------------------------------------------------------------------
__global__ void __launch_bounds__(256, 1)
sim_topk_kernel(const float* __restrict__ keys,
                const float* __restrict__ importance,
                int N) {
    extern __shared__ unsigned smw[];
    const int tid = threadIdx.x, g = blockIdx.x;

    // roles
    const int kg = tid & 31, dg = tid >> 5;   // loader: keys 4kg..+3, dims 16dg..+15
    const int rg = tid >> 4, cg = tid & 15;   // GEMM: m 4rg..+3, n 8cg..+7
    const int rr = tid >> 2, ssn = tid & 3;   // scan: 4 scanners/row

    // --- stage Q^T bf16 [d][m], row stride QWW
    {
        int d = tid >> 1, half = tid & 1;
        const uint4* src = (const uint4*)g_qTbf + d*8 + half*4;
        unsigned* dst = smw + OFF_QT + d*QWW + half*16;
        #pragma unroll
        for (int j = 0; j < 4; j++) *(uint4*)(dst + 4*j) = src[j];
    }

    const int T = (N + TILE - 1) / TILE;

    float4 pf[4][4];        // staged next tile: [key][jj] (dims 16dg+4jj..+3)
    float  rimp = 0.f;

    // LDG phase: global -> registers (latency hidden behind GEMM)
    auto ldgK = [&](int t) {
        int base = t * TILE;
        #pragma unroll
        for (int kk = 0; kk < 4; kk++) {
            int gk = base + 4*kg + kk;
            bool valid = gk < N;
            const float4* kr = (const float4*)(keys + (size_t)gk*D + 16*dg);
            #pragma unroll
            for (int jj = 0; jj < 4; jj++)
                pf[kk][jj] = valid ? kr[jj] : make_float4(0.f,0.f,0.f,0.f);
        }
        if (tid < 128) rimp = (base + tid < N) ? importance[base + tid] : 0.f;
    };

    // STS phase: registers -> K^T bf16 [d][n] + ssq partials + importance
    auto stsK = [&](int buf) {
        unsigned* K = smw + (buf ? OFF_K1 : OFF_K0);
        float* ssqp = (float*)(smw + OFF_SSQ) + buf*8*SIM_LD;
        float sq0=0.f, sq1=0.f, sq2=0.f, sq3=0.f;
        #pragma unroll
        for (int jj = 0; jj < 4; jj++) {
            float4 a = pf[0][jj], b = pf[1][jj], c = pf[2][jj], e = pf[3][jj];
            sq0 += a.x*a.x + a.y*a.y + a.z*a.z + a.w*a.w;
            sq1 += b.x*b.x + b.y*b.y + b.z*b.z + b.w*b.w;
            sq2 += c.x*c.x + c.y*c.y + c.z*c.z + c.w*c.w;
            sq3 += e.x*e.x + e.y*e.y + e.z*e.z + e.w*e.w;
            int d0 = 16*dg + 4*jj;
            unsigned w01, w23;
            CVT2(w01, b.x, a.x); CVT2(w23, e.x, c.x);
            *(uint2*)(K + (d0+0)*KWW + 2*kg) = make_uint2(w01, w23);
            CVT2(w01, b.y, a.y); CVT2(w23, e.y, c.y);
            *(uint2*)(K + (d0+1)*KWW + 2*kg) = make_uint2(w01, w23);
            CVT2(w01, b.z, a.z); CVT2(w23, e.z, c.z);
            *(uint2*)(K + (d0+2)*KWW + 2*kg) = make_uint2(w01, w23);
            CVT2(w01, b.w, a.w); CVT2(w23, e.w, c.w);
            *(uint2*)(K + (d0+3)*KWW + 2*kg) = make_uint2(w01, w23);
        }
        *(float4*)(ssqp + dg*SIM_LD + 4*kg) = make_float4(sq0,sq1,sq2,sq3);
        if (tid < 128) ((float*)(smw + OFF_IMP))[buf*128 + tid] = rimp;
    };

    // running top-8 per (row, col-slice) stream
    float tv[KTOP]; int tix[KTOP];
    #pragma unroll
    for (int k = 0; k < KTOP; k++) { tv[k] = -INFINITY; tix[k] = 0; }
    float vmin = -INFINITY; int minpos = 0;

    if (g < T) { ldgK(g); stsK(0); }
    __syncthreads();
    int cur = 0;

    for (int tc = g; tc < T; tc += G2, cur ^= 1) {
        const int base = tc * TILE;
        const unsigned* Kt = smw + (cur ? OFF_K1 : OFF_K0);
        const unsigned* Qt = smw + OFF_QT;

        // A: per-key scale = importance / max(||k||,eps)  (threads 0..127)
        if (tid < 128) {
            const float* ssqp = (const float*)(smw + OFF_SSQ) + cur*8*SIM_LD;
            float ssq = 0.f;
            #pragma unroll
            for (int j = 0; j < 8; j++) ssq += ssqp[j*SIM_LD + tid];
            float imp = ((const float*)(smw + OFF_IMP))[cur*128 + tid];
            ((float*)(smw + OFF_SCL))[cur*128 + tid] =
                imp / fmaxf(sqrtf(ssq), 1e-12f);
        }

        // B: issue next tile's LDGs (registers; hidden behind GEMM)
        const int tn = tc + G2;
        const bool haven = tn < T;
        if (haven) ldgK(tn);

        // C: HFMA2 GEMM — 4m x 8n per thread, dual bf16x2 chains
        __nv_bfloat162 acc1[16], acc2[16];
        {
            __nv_bfloat162 z = __float2bfloat162_rn(0.f);
            #pragma unroll
            for (int i = 0; i < 16; i++) { acc1[i] = z; acc2[i] = z; }
        }
        #pragma unroll 4
        for (int d = 0; d < D; d += 2) {
            uint2 q1 = *(const uint2*)(Qt + d*QWW + rg*2);
            uint4 k1 = *(const uint4*)(Kt + d*KWW + cg*4);
            uint2 q2 = *(const uint2*)(Qt + (d+1)*QWW + rg*2);
            uint4 k2 = *(const uint4*)(Kt + (d+1)*KWW + cg*4);
            {
                __nv_bfloat162 qx = *(__nv_bfloat162*)&q1.x;
                __nv_bfloat162 qy = *(__nv_bfloat162*)&q1.y;
                __nv_bfloat162 a0 = __low2bfloat162(qx), a1 = __high2bfloat162(qx);
                __nv_bfloat162 a2 = __low2bfloat162(qy), a3 = __high2bfloat162(qy);
                __nv_bfloat162 b0 = *(__nv_bfloat162*)&k1.x, b1 = *(__nv_bfloat162*)&k1.y;
                __nv_bfloat162 b2 = *(__nv_bfloat162*)&k1.z, b3 = *(__nv_bfloat162*)&k1.w;
                acc1[0]  = __hfma2(a0,b0,acc1[0]);  acc1[1]  = __hfma2(a0,b1,acc1[1]);
                acc1[2]  = __hfma2(a0,b2,acc1[2]);  acc1[3]  = __hfma2(a0,b3,acc1[3]);
                acc1[4]  = __hfma2(a1,b0,acc1[4]);  acc1[5]  = __hfma2(a1,b1,acc1[5]);
                acc1[6]  = __hfma2(a1,b2,acc1[6]);  acc1[7]  = __hfma2(a1,b3,acc1[7]);
                acc1[8]  = __hfma2(a2,b0,acc1[8]);  acc1[9]  = __hfma2(a2,b1,acc1[9]);
                acc1[10] = __hfma2(a2,b2,acc1[10]); acc1[11] = __hfma2(a2,b3,acc1[11]);
                acc1[12] = __hfma2(a3,b0,acc1[12]); acc1[13] = __hfma2(a3,b1,acc1[13]);
                acc1[14] = __hfma2(a3,b2,acc1[14]); acc1[15] = __hfma2(a3,b3,acc1[15]);
            }
            {
                __nv_bfloat162 qx = *(__nv_bfloat162*)&q2.x;
                __nv_bfloat162 qy = *(__nv_bfloat162*)&q2.y;
                __nv_bfloat162 a0 = __low2bfloat162(qx), a1 = __high2bfloat162(qx);
                __nv_bfloat162 a2 = __low2bfloat162(qy), a3 = __high2bfloat162(qy);
                __nv_bfloat162 b0 = *(__nv_bfloat162*)&k2.x, b1 = *(__nv_bfloat162*)&k2.y;
                __nv_bfloat162 b2 = *(__nv_bfloat162*)&k2.z, b3 = *(__nv_bfloat162*)&k2.w;
                acc2[0]  = __hfma2(a0,b0,acc2[0]);  acc2[1]  = __hfma2(a0,b1,acc2[1]);
                acc2[2]  = __hfma2(a0,b2,acc2[2]);  acc2[3]  = __hfma2(a0,b3,acc2[3]);
                acc2[4]  = __hfma2(a1,b0,acc2[4]);  acc2[5]  = __hfma2(a1,b1,acc2[5]);
                acc2[6]  = __hfma2(a1,b2,acc2[6]);  acc2[7]  = __hfma2(a1,b3,acc2[7]);
                acc2[8]  = __hfma2(a2,b0,acc2[8]);  acc2[9]  = __hfma2(a2,b1,acc2[9]);
                acc2[10] = __hfma2(a2,b2,acc2[10]); acc2[11] = __hfma2(a2,b3,acc2[11]);
                acc2[12] = __hfma2(a3,b0,acc2[12]); acc2[13] = __hfma2(a3,b1,acc2[13]);
                acc2[14] = __hfma2(a3,b2,acc2[14]); acc2[15] = __hfma2(a3,b3,acc2[15]);
            }
        }

        // C2: store staged next tile (other buffer)
        if (haven) stsK(cur ^ 1);

        __syncthreads();   // D: scl visible; prev scan done (sims writable)

        // E: fp32 combine + scale -> sims [m][n]
        {
            const float* sclp = (const float*)(smw + OFF_SCL) + cur*128;
            float* simsF = (float*)(smw + OFF_SIM);
            int n0 = 8*cg;
            float s4[8];
            #pragma unroll
            for (int m = 0; m < 4; m++) {
                #pragma unroll
                for (int j = 0; j < 4; j++) {
                    __nv_bfloat162 v1 = acc1[m*4+j], v2 = acc2[m*4+j];
                    s4[2*j]   = (__bfloat162float(v1.x) + __bfloat162float(v2.x)) * sclp[n0+2*j];
                    s4[2*j+1] = (__bfloat162float(v1.y) + __bfloat162float(v2.y)) * sclp[n0+2*j+1];
                }
                int row = 4*rg + m;
                *(float4*)(simsF + row*SIM_LD + n0)     = make_float4(s4[0],s4[1],s4[2],s4[3]);
                *(float4*)(simsF + row*SIM_LD + n0 + 4) = make_float4(s4[4],s4[5],s4[6],s4[7]);
            }
        }
        __syncthreads();   // F: sims visible

        // G: running top-8 — scanner ssn takes cols ssn+4n (conflict-free)
        {
            const float* sr = (const float*)(smw + OFF_SIM) + rr*SIM_LD + ssn;
            #pragma unroll 4
            for (int n = 0; n < 32; n++) {
                float v = sr[4*n];
                int idx = base + ssn + 4*n;
                if (idx < N && v > vmin) {
                    tv[minpos] = v; tix[minpos] = idx;
                    vmin = tv[0]; minpos = 0;
                    #pragma unroll
                    for (int k = 1; k < KTOP; k++)
                        if (tv[k] < vmin) { vmin = tv[k]; minpos = k; }
                }
            }
        }
        // next iter's sync D orders this scan before sims overwrite
    }

    // --- merge 4 scanner streams per row -> 8 candidates per row
    __syncthreads();
    float* bufv = (float*)(smw + OFF_K0);          // alias K0 (loop done)
    int*   bufi = (int*)(smw + OFF_K0 + 2048);
    #pragma unroll
    for (int k = 0; k < KTOP; k++) { bufv[tid*KTOP + k] = tv[k]; bufi[tid*KTOP + k] = tix[k]; }
    __syncthreads();
    if (tid < 64) {
        float fv[KTOP]; int fi[KTOP];
        #pragma unroll
        for (int k = 0; k < KTOP; k++) { fv[k] = -INFINITY; fi[k] = 0; }
        float fmin = -INFINITY; int fpos = 0;
        int e0 = (4*tid)*KTOP;
        for (int e = 0; e < 4*KTOP; e++) {
            float v = bufv[e0 + e];
            if (v > fmin) {
                fv[fpos] = v; fi[fpos] = bufi[e0 + e];
                fmin = fv[0]; fpos = 0;
                #pragma unroll
                for (int k = 1; k < KTOP; k++)
                    if (fv[k] < fmin) { fmin = fv[k]; fpos = k; }
            }
        }
        int o = tid*NCAND + g*KTOP;
        #pragma unroll
        for (int k = 0; k < KTOP; k++) { g_cval[o+k] = fv[k]; g_cidx[o+k] = fi[k]; }
    }
}

// ---------------------------------------------------------------------------
// Kernel 3: merge candidates -> approx top-M1 -> EXACT fp32 rescore -> top-8,
// gather values, softmax attention, combine, out = mem @ W_comb^T + b_comb
// ---------------------------------------------------------------------------
__global__ void final_kernel(const float* __restrict__ keys,
                             const float* __restrict__ values,
                             const float* __restrict__ importance,
                             const float* __restrict__ w_attn,
                             const float* __restrict__ b_attn,
                             const float* __restrict__ Wcomb,
                             const float* __restrict__ bcomb,
                             float* __restrict__ out,
                             int N) {
    __shared__ float cv[NCAND];
    __shared__ int   ci[NCAND];
    __shared__ float rv[8];
    __shared__ int   rp[8];
    __shared__ int   candIdx[M1];
    __shared__ float rs[M1];
    __shared__ float qrow[D];
    __shared__ int   topidx[KTOP];
    __shared__ float vs[KTOP*129];
    __shared__ float wa[D];
    __shared__ float ts[KTOP];
    __shared__ float sc[KTOP];
    __shared__ float ms[D];

    const int b = blockIdx.x;
    const int tid = threadIdx.x;          // 256 threads
    const int wid = tid >> 5, lane = tid & 31;

    for (int i = tid; i < NCAND; i += 256) {
        cv[i] = g_cval[b*NCAND + i];
        ci[i] = g_cidx[b*NCAND + i];
    }
    if (tid < D) { wa[tid] = w_attn[tid]; qrow[tid] = g_qRow[b*D + tid]; }
    __syncthreads();

    // M1 rounds of argmax (warp-shuffle reduce)
    for (int k = 0; k < M1; k++) {
        float best = -INFINITY; int bp = 0;
        for (int i = tid; i < NCAND; i += 256)
            if (cv[i] > best) { best = cv[i]; bp = i; }
        #pragma unroll
        for (int off = 16; off; off >>= 1) {
            float ov = __shfl_xor_sync(0xffffffff, best, off);
            int   oi = __shfl_xor_sync(0xffffffff, bp, off);
            if (ov > best) { best = ov; bp = oi; }
        }
        if (lane == 0) { rv[wid] = best; rp[wid] = bp; }
        __syncthreads();
        if (tid == 0) {
            float bb = rv[0]; int bi = rp[0];
            #pragma unroll
            for (int w = 1; w < 8; w++)
                if (rv[w] > bb) { bb = rv[w]; bi = rp[w]; }
            candIdx[k] = ci[bi];
            cv[bi] = -INFINITY;
        }
        __syncthreads();
    }

    // EXACT fp32 rescore of the M1 candidates (one warp per candidate)
    for (int j = wid; j < M1; j += 8) {
        int idx = candIdx[j];
        idx = idx < 0 ? 0 : (idx >= N ? N-1 : idx);
        const float4* kr = reinterpret_cast<const float4*>(keys + (size_t)idx * D);
        float4 k4 = kr[lane];
        float4 q4 = *reinterpret_cast<const float4*>(qrow + 4*lane);
        float dot = q4.x*k4.x + q4.y*k4.y + q4.z*k4.z + q4.w*k4.w;
        float ssq = k4.x*k4.x + k4.y*k4.y + k4.z*k4.z + k4.w*k4.w;
        dot = warpsum(dot);
        ssq = warpsum(ssq);
        if (lane == 0)
            rs[j] = importance[idx] * dot / fmaxf(sqrtf(ssq), 1e-12f);
    }
    __syncthreads();

    // exact top-8 of the M1 rescored candidates
    if (tid == 0) {
        #pragma unroll
        for (int k = 0; k < KTOP; k++) {
            float best = -INFINITY; int bp = 0;
            for (int j = 0; j < M1; j++)
                if (rs[j] > best) { best = rs[j]; bp = j; }
            topidx[k] = candIdx[bp];
            rs[bp] = -INFINITY;
        }
    }
    __syncthreads();

    // gather retrieved values
    if (tid < D) {
        #pragma unroll
        for (int k = 0; k < KTOP; k++)
            vs[k*129 + tid] = values[(size_t)topidx[k]*D + tid];
    }
    __syncthreads();

    // attention logits
    if (tid < KTOP) {
        float acc = b_attn[0];
        for (int d = 0; d < D; d++) acc += vs[tid*129 + d] * wa[d];
        ts[tid] = acc;
    }
    __syncthreads();
    if (tid == 0) {
        float mx = ts[0];
        #pragma unroll
        for (int k = 1; k < KTOP; k++) mx = fmaxf(mx, ts[k]);
        float e[KTOP]; float s = 0.f;
        #pragma unroll
        for (int k = 0; k < KTOP; k++) { e[k] = expf(ts[k] - mx); s += e[k]; }
        #pragma unroll
        for (int k = 0; k < KTOP; k++) sc[k] = e[k] / s;
    }
    __syncthreads();

    // weighted memory
    if (tid < D) {
        float mm = 0.f;
        #pragma unroll
        for (int k = 0; k < KTOP; k++) mm += sc[k] * vs[k*129 + tid];
        ms[tid] = mm;
    }
    __syncthreads();

    // out = mem @ W_comb^T + b_comb  (warp-coalesced matvec)
    for (int d = wid; d < D; d += 8) {
        const float* wr = Wcomb + (size_t)d*D;
        float acc = 0.f;
        #pragma unroll
        for (int j = 0; j < 4; j++) {
            int e = lane + 32*j;
            acc += ms[e] * wr[e];
        }
        acc = warpsum(acc);
        if (lane == 0) out[b*D + d] = acc + bcomb[d];
    }
}

// ---------------------------------------------------------------------------
extern "C" void kernel_launch(void* const* d_in, const int* in_sizes, int n_in,
                              void* d_out, int out_size) {
    const float* query      = (const float*)d_in[0];
    const float* keys       = (const float*)d_in[1];
    const float* values     = (const float*)d_in[2];
    const float* importance = (const float*)d_in[3];
    const float* Wq         = (const float*)d_in[4];
    const float* bq         = (const float*)d_in[5];
    const float* w_attn     = (const float*)d_in[6];
    const float* b_attn     = (const float*)d_in[7];
    const float* Wcomb      = (const float*)d_in[8];
    const float* bcomb      = (const float*)d_in[9];
    const int N = in_sizes[1] / D;

    const size_t smem2_bytes = (size_t)SMEM_WORDS * 4;
    cudaFuncSetAttribute(sim_topk_kernel,
                         cudaFuncAttributeMaxDynamicSharedMemorySize, (int)smem2_bytes);

    qproj_kernel<<<512, 256>>>(query, Wq, bq);
    sim_topk_kernel<<<G2, 256, smem2_bytes>>>(keys, importance, N);
    final_kernel<<<B, 256>>>(keys, values, importance, w_attn, b_attn,
                             Wcomb, bcomb, (float*)d_out, N);
}

// round 17
// speedup vs baseline: 1.4152x; 1.4152x over previous
#include <cuda_runtime.h>
#include <cuda_bf16.h>
#include <math.h>

#define B 64
#define C 256
#define D 128
#define KTOP 8
#define G2 296
#define TILE 128
#define NCAND (G2*KTOP)     // 2368
#define M1 16               // exact-rescore window
#define KW 68               // bf16 row stride in 32-bit words (68%32=4 -> conflict-free frags)
#define SIM_LD 132          // sims fp32 row stride

// smem layout in 32-bit words
#define OFF_QW   0                    // Q bf16: 64 rows x 68 words = 4352
#define OFF_K0   4352                 // K bf16 buf0: 128 x 68 = 8704
#define OFF_K1   (4352 + 8704)        // 13056
#define OFF_SCL  (13056 + 8704)       // 21760: scale[128]
#define SMEM_WORDS (21760 + 128)      // 21888 words = 87552 B -> 2 CTAs/SM

// scratch (device globals: no allocations allowed)
__device__ float g_qRow[B*D];         // q (unnormalized) row-major [b][d]
__device__ float g_cval[B*NCAND];     // per-block top-8 values (bf16-mma scores)
__device__ int   g_cidx[B*NCAND];     // per-block top-8 indices

__device__ __forceinline__ float warpsum(float v) {
    v += __shfl_xor_sync(0xffffffff, v, 16);
    v += __shfl_xor_sync(0xffffffff, v, 8);
    v += __shfl_xor_sync(0xffffffff, v, 4);
    v += __shfl_xor_sync(0xffffffff, v, 2);
    v += __shfl_xor_sync(0xffffffff, v, 1);
    return v;
}

// bf16x2 pack: w = {hi: cvt(h), lo: cvt(l)}
#define CVT2(w, h, l) \
    asm("cvt.rn.bf16x2.f32 %0, %1, %2;" : "=r"(w) : "f"(h), "f"(l))

// m16n8k16 bf16 MMA, fp32 accumulate
#define MMA_BF16(d0,d1,d2,d3, a0,a1,a2,a3, b0,b1) \
    asm("mma.sync.aligned.m16n8k16.row.col.f32.bf16.bf16.f32 " \
        "{%0,%1,%2,%3}, {%4,%5,%6,%7}, {%8,%9}, {%0,%1,%2,%3};" \
        : "+f"(d0), "+f"(d1), "+f"(d2), "+f"(d3) \
        : "r"(a0), "r"(a1), "r"(a2), "r"(a3), "r"(b0), "r"(b1))

// ---------------------------------------------------------------------------
// Kernel 1: q = query @ W_q^T + b_q  (no normalization: positive per-row scale
// is top-k order invariant and sim values are selection-only).
// ---------------------------------------------------------------------------
__global__ void qproj_kernel(const float* __restrict__ query,
                             const float* __restrict__ Wq,
                             const float* __restrict__ bq) {
    const int gw   = (blockIdx.x * blockDim.x + threadIdx.x) >> 5;  // 0..4095
    const int lane = threadIdx.x & 31;
    const int b    = gw >> 6;           // 0..63
    const int d0   = (gw & 63) << 1;    // 0,2,...,126

    const float* qr = query + (size_t)b * C;
    const float* w0 = Wq + (size_t)(d0 + 0) * C;
    const float* w1 = Wq + (size_t)(d0 + 1) * C;

    float a0 = 0.f, a1 = 0.f;
    #pragma unroll
    for (int j = 0; j < 8; j++) {
        int c = lane + 32 * j;
        float q = __ldg(qr + c);
        a0 += q * __ldg(w0 + c);
        a1 += q * __ldg(w1 + c);
    }
    #pragma unroll
    for (int off = 16; off; off >>= 1) {
        a0 += __shfl_xor_sync(0xffffffff, a0, off);
        a1 += __shfl_xor_sync(0xffffffff, a1, off);
    }
    if (lane == 0) {
        g_qRow[b*D + d0 + 0] = a0 + bq[d0 + 0];
        g_qRow[b*D + d0 + 1] = a1 + bq[d0 + 1];
    }
}

// ---------------------------------------------------------------------------
// Kernel 2: 64x128 sim tile via bf16 m16n8k16 MMA on NATURAL-layout operands
// (no transpose), double-buffered bf16 key tiles, TRUE 2 CTAs/SM (grid 296),
// running top-8. Exactness restored by fp32 rescore of top-M1 in kernel 3.
// ---------------------------------------------------------------------------
__global__ void __launch_bounds__(256, 2)
sim_topk_kernel(const float* __restrict__ keys,
                const float* __restrict__ importance,
                int N) {
    extern __shared__ unsigned smw[];          // word-addressed smem
    unsigned* Qw  = smw + OFF_QW;
    float*    scl = (float*)(smw + OFF_SCL);

    const int tid = threadIdx.x;               // 256 threads
    const int g   = blockIdx.x;
    const int wid = tid >> 5, lane = tid & 31;
    const int wm  = wid & 1,  wn  = wid >> 1;  // MMA warp grid 2x4
    const int gid = lane >> 2, tig = lane & 3; // fragment coords
    const int rr  = tid >> 2, ss = tid & 3;    // scan: 4 scanners per row

    // --- resident Q in bf16 natural layout [m][k]: warp w loads rows w+8i
    {
        const float4* qsrc = (const float4*)g_qRow;
        #pragma unroll
        for (int i = 0; i < 8; i++) {
            int r = wid + 8*i;                 // 0..63
            float4 v = qsrc[r*32 + lane];
            unsigned wlo, whi;
            CVT2(wlo, v.y, v.x);
            CVT2(whi, v.w, v.z);
            *reinterpret_cast<uint2*>(Qw + r*KW + lane*2) = make_uint2(wlo, whi);
        }
    }

    // running top-8 per (row, col-slice) stream
    float tv[KTOP]; int tix[KTOP];
    #pragma unroll
    for (int k = 0; k < KTOP; k++) { tv[k] = -INFINITY; tix[k] = 0; }
    float vmin = -INFINITY; int minpos = 0;

    const int T = (N + TILE - 1) / TILE;

    // --- coalesced loader: warp w handles rows w+8i; lane = float4 of row
    auto loadK = [&](int t, unsigned* Kw) {
        int base = t * TILE;
        #pragma unroll 4
        for (int i = 0; i < 16; i++) {
            int r  = wid + 8*i;                // 0..127
            int gk = base + r;
            float4 v = make_float4(0.f,0.f,0.f,0.f);
            if (gk < N)
                v = reinterpret_cast<const float4*>(keys)[(size_t)gk*32 + lane];
            unsigned wlo, whi;
            CVT2(wlo, v.y, v.x);
            CVT2(whi, v.w, v.z);
            *reinterpret_cast<uint2*>(Kw + r*KW + lane*2) = make_uint2(wlo, whi);
        }
    };

    if (g < T) loadK(g, smw + OFF_K0);
    __syncthreads();
    int cur = 0;

    for (int tc = g; tc < T; tc += G2, cur ^= 1) {
        unsigned* Kw = smw + (cur ? OFF_K1 : OFF_K0);
        const int base = tc * TILE;
        const int tn = tc + G2;
        const bool haven = tn < T;

        // --- stage next tile (writes other buffer; overlaps MMA)
        if (haven) loadK(tn, smw + (cur ? OFF_K0 : OFF_K1));

        // --- per-key scale = importance / max(||k||,eps) from bf16 row
        if (tid < 128) {
            int gk = base + tid;
            float ssq = 0.f;
            const uint4* row = reinterpret_cast<const uint4*>(Kw + tid*KW);
            #pragma unroll
            for (int u = 0; u < 16; u++) {     // 64 valid words = 16 uint4
                uint4 w4 = row[u];
                float2 f;
                f = __bfloat1622float2(*reinterpret_cast<const __nv_bfloat162*>(&w4.x)); ssq += f.x*f.x + f.y*f.y;
                f = __bfloat1622float2(*reinterpret_cast<const __nv_bfloat162*>(&w4.y)); ssq += f.x*f.x + f.y*f.y;
                f = __bfloat1622float2(*reinterpret_cast<const __nv_bfloat162*>(&w4.z)); ssq += f.x*f.x + f.y*f.y;
                f = __bfloat1622float2(*reinterpret_cast<const __nv_bfloat162*>(&w4.w)); ssq += f.x*f.x + f.y*f.y;
            }
            float imp = (gk < N) ? importance[gk] : 0.f;
            scl[tid] = imp / fmaxf(sqrtf(ssq), 1e-12f);
        }

        // --- MMA: 2 M-tiles x 4 N-strips x 8 k16-steps, natural layouts
        float acc[2][4][4];
        #pragma unroll
        for (int mt = 0; mt < 2; mt++)
            #pragma unroll
            for (int sn = 0; sn < 4; sn++)
                #pragma unroll
                for (int r = 0; r < 4; r++) acc[mt][sn][r] = 0.f;

        const int bm = 32*wm, bn = 32*wn;
        #pragma unroll
        for (int wk0 = 0; wk0 < 64; wk0 += 8) {      // word k-offset
            unsigned a[2][4], b[4][2];
            #pragma unroll
            for (int mt = 0; mt < 2; mt++) {
                const unsigned* qa = Qw + (bm + 16*mt + gid)*KW + wk0 + tig;
                a[mt][0] = qa[0];
                a[mt][1] = qa[8*KW];
                a[mt][2] = qa[4];
                a[mt][3] = qa[8*KW + 4];
            }
            #pragma unroll
            for (int sn = 0; sn < 4; sn++) {
                const unsigned* kb = Kw + (bn + 8*sn + gid)*KW + wk0 + tig;
                b[sn][0] = kb[0];
                b[sn][1] = kb[4];
            }
            #pragma unroll
            for (int mt = 0; mt < 2; mt++)
                #pragma unroll
                for (int sn = 0; sn < 4; sn++)
                    MMA_BF16(acc[mt][sn][0], acc[mt][sn][1], acc[mt][sn][2], acc[mt][sn][3],
                             a[mt][0], a[mt][1], a[mt][2], a[mt][3],
                             b[sn][0], b[sn][1]);
        }

        __syncthreads();   // 1: K[cur] reads done (mma+ssq); K[nxt] staged; scl visible

        // --- scaled sims into K[cur] region as fp32 [64][SIM_LD]
        float* simsF = (float*)Kw;
        #pragma unroll
        for (int mt = 0; mt < 2; mt++) {
            int r0 = bm + 16*mt + gid;
            #pragma unroll
            for (int sn = 0; sn < 4; sn++) {
                int c0 = bn + 8*sn + 2*tig;
                float s0 = scl[c0], s1 = scl[c0+1];
                simsF[r0*SIM_LD + c0]         = acc[mt][sn][0] * s0;
                simsF[r0*SIM_LD + c0 + 1]     = acc[mt][sn][1] * s1;
                simsF[(r0+8)*SIM_LD + c0]     = acc[mt][sn][2] * s0;
                simsF[(r0+8)*SIM_LD + c0 + 1] = acc[mt][sn][3] * s1;
            }
        }
        __syncthreads();   // 2: sims visible

        // --- running top-8: scanner ss takes cols ss, ss+4, ... (conflict-free)
        {
            float* simsF2 = (float*)Kw;
            int nmax = N - base; if (nmax > TILE) nmax = TILE;
            int cnt = (nmax > ss) ? ((nmax - ss + 3) >> 2) : 0;
            const float* sr = simsF2 + rr*SIM_LD + ss;
            for (int n = 0; n < cnt; n++) {
                float v = sr[4*n];
                if (v > vmin) {
                    tv[minpos] = v; tix[minpos] = base + 4*n + ss;
                    vmin = tv[0]; minpos = 0;
                    #pragma unroll
                    for (int k = 1; k < KTOP; k++)
                        if (tv[k] < vmin) { vmin = tv[k]; minpos = k; }
                }
            }
        }
        __syncthreads();   // 3: scan done -> next iter may overwrite K[cur]
    }

    // --- merge 4 scanner streams per row -> 8 candidates per row
    float* bufv = (float*)(smw + OFF_QW);          // alias Q region (done)
    int*   bufi = (int*)(smw + OFF_QW + 2048);
    #pragma unroll
    for (int k = 0; k < KTOP; k++) { bufv[tid*KTOP + k] = tv[k]; bufi[tid*KTOP + k] = tix[k]; }
    __syncthreads();
    if (tid < 64) {
        float fv[KTOP]; int fi[KTOP];
        #pragma unroll
        for (int k = 0; k < KTOP; k++) { fv[k] = -INFINITY; fi[k] = 0; }
        float fmin = -INFINITY; int fpos = 0;
        int e0 = (4*tid)*KTOP;
        for (int e = 0; e < 4*KTOP; e++) {
            float v = bufv[e0 + e];
            if (v > fmin) {
                fv[fpos] = v; fi[fpos] = bufi[e0 + e];
                fmin = fv[0]; fpos = 0;
                #pragma unroll
                for (int k = 1; k < KTOP; k++)
                    if (fv[k] < fmin) { fmin = fv[k]; fpos = k; }
            }
        }
        int o = tid*NCAND + g*KTOP;
        #pragma unroll
        for (int k = 0; k < KTOP; k++) { g_cval[o+k] = fv[k]; g_cidx[o+k] = fi[k]; }
    }
}

// ---------------------------------------------------------------------------
// Kernel 3: merge candidates -> approx top-M1 -> EXACT fp32 rescore -> top-8,
// gather values, softmax attention, combine, out = mem @ W_comb^T + b_comb
// ---------------------------------------------------------------------------
__global__ void final_kernel(const float* __restrict__ keys,
                             const float* __restrict__ values,
                             const float* __restrict__ importance,
                             const float* __restrict__ w_attn,
                             const float* __restrict__ b_attn,
                             const float* __restrict__ Wcomb,
                             const float* __restrict__ bcomb,
                             float* __restrict__ out,
                             int N) {
    __shared__ float cv[NCAND];
    __shared__ int   ci[NCAND];
    __shared__ float rv[8];
    __shared__ int   rp[8];
    __shared__ int   candIdx[M1];
    __shared__ float rs[M1];
    __shared__ float qrow[D];
    __shared__ int   topidx[KTOP];
    __shared__ float vs[KTOP*129];
    __shared__ float wa[D];
    __shared__ float ts[KTOP];
    __shared__ float sc[KTOP];
    __shared__ float ms[D];

    const int b = blockIdx.x;
    const int tid = threadIdx.x;          // 256 threads
    const int wid = tid >> 5, lane = tid & 31;

    for (int i = tid; i < NCAND; i += 256) {
        cv[i] = g_cval[b*NCAND + i];
        ci[i] = g_cidx[b*NCAND + i];
    }
    if (tid < D) { wa[tid] = w_attn[tid]; qrow[tid] = g_qRow[b*D + tid]; }
    __syncthreads();

    // M1 rounds of argmax (warp-shuffle reduce, 2 syncs/round)
    for (int k = 0; k < M1; k++) {
        float best = -INFINITY; int bp = 0;
        for (int i = tid; i < NCAND; i += 256)
            if (cv[i] > best) { best = cv[i]; bp = i; }
        #pragma unroll
        for (int off = 16; off; off >>= 1) {
            float ov = __shfl_xor_sync(0xffffffff, best, off);
            int   oi = __shfl_xor_sync(0xffffffff, bp, off);
            if (ov > best) { best = ov; bp = oi; }
        }
        if (lane == 0) { rv[wid] = best; rp[wid] = bp; }
        __syncthreads();
        if (tid == 0) {
            float bb = rv[0]; int bi = rp[0];
            #pragma unroll
            for (int w = 1; w < 8; w++)
                if (rv[w] > bb) { bb = rv[w]; bi = rp[w]; }
            candIdx[k] = ci[bi];
            cv[bi] = -INFINITY;
        }
        __syncthreads();
    }

    // EXACT fp32 rescore of the M1 candidates (one warp per candidate)
    for (int j = wid; j < M1; j += 8) {
        int idx = candIdx[j];
        idx = idx < 0 ? 0 : (idx >= N ? N-1 : idx);
        const float4* kr = reinterpret_cast<const float4*>(keys + (size_t)idx * D);
        float4 k4 = kr[lane];
        float4 q4 = *reinterpret_cast<const float4*>(qrow + 4*lane);
        float dot = q4.x*k4.x + q4.y*k4.y + q4.z*k4.z + q4.w*k4.w;
        float ssq = k4.x*k4.x + k4.y*k4.y + k4.z*k4.z + k4.w*k4.w;
        dot = warpsum(dot);
        ssq = warpsum(ssq);
        if (lane == 0)
            rs[j] = importance[idx] * dot / fmaxf(sqrtf(ssq), 1e-12f);
    }
    __syncthreads();

    // exact top-8 of the M1 rescored candidates
    if (tid == 0) {
        #pragma unroll
        for (int k = 0; k < KTOP; k++) {
            float best = -INFINITY; int bp = 0;
            for (int j = 0; j < M1; j++)
                if (rs[j] > best) { best = rs[j]; bp = j; }
            topidx[k] = candIdx[bp];
            rs[bp] = -INFINITY;
        }
    }
    __syncthreads();

    // gather retrieved values
    if (tid < D) {
        #pragma unroll
        for (int k = 0; k < KTOP; k++)
            vs[k*129 + tid] = values[(size_t)topidx[k]*D + tid];
    }
    __syncthreads();

    // attention logits
    if (tid < KTOP) {
        float acc = b_attn[0];
        for (int d = 0; d < D; d++) acc += vs[tid*129 + d] * wa[d];
        ts[tid] = acc;
    }
    __syncthreads();
    if (tid == 0) {
        float mx = ts[0];
        #pragma unroll
        for (int k = 1; k < KTOP; k++) mx = fmaxf(mx, ts[k]);
        float e[KTOP]; float s = 0.f;
        #pragma unroll
        for (int k = 0; k < KTOP; k++) { e[k] = expf(ts[k] - mx); s += e[k]; }
        #pragma unroll
        for (int k = 0; k < KTOP; k++) sc[k] = e[k] / s;
    }
    __syncthreads();

    // weighted memory
    if (tid < D) {
        float mm = 0.f;
        #pragma unroll
        for (int k = 0; k < KTOP; k++) mm += sc[k] * vs[k*129 + tid];
        ms[tid] = mm;
    }
    __syncthreads();

    // out = mem @ W_comb^T + b_comb  (warp-coalesced matvec)
    for (int d = wid; d < D; d += 8) {
        const float* wr = Wcomb + (size_t)d*D;
        float acc = 0.f;
        #pragma unroll
        for (int j = 0; j < 4; j++) {
            int e = lane + 32*j;
            acc += ms[e] * wr[e];
        }
        acc = warpsum(acc);
        if (lane == 0) out[b*D + d] = acc + bcomb[d];
    }
}

// ---------------------------------------------------------------------------
extern "C" void kernel_launch(void* const* d_in, const int* in_sizes, int n_in,
                              void* d_out, int out_size) {
    const float* query      = (const float*)d_in[0];
    const float* keys       = (const float*)d_in[1];
    const float* values     = (const float*)d_in[2];
    const float* importance = (const float*)d_in[3];
    const float* Wq         = (const float*)d_in[4];
    const float* bq         = (const float*)d_in[5];
    const float* w_attn     = (const float*)d_in[6];
    const float* b_attn     = (const float*)d_in[7];
    const float* Wcomb      = (const float*)d_in[8];
    const float* bcomb      = (const float*)d_in[9];
    const int N = in_sizes[1] / D;

    const size_t smem2_bytes = (size_t)SMEM_WORDS * 4;
    cudaFuncSetAttribute(sim_topk_kernel,
                         cudaFuncAttributeMaxDynamicSharedMemorySize, (int)smem2_bytes);

    qproj_kernel<<<512, 256>>>(query, Wq, bq);
    sim_topk_kernel<<<G2, 256, smem2_bytes>>>(keys, importance, N);
    final_kernel<<<B, 256>>>(keys, values, importance, w_attn, b_attn,
                             Wcomb, bcomb, (float*)d_out, N);
}